// round 10
// baseline (speedup 1.0000x reference)
#include <cuda_runtime.h>
#include <math.h>
#include <stdint.h>

#define BATCH   16
#define N_PEP   128
#define M_PRO   2048
#define HEADS   8
#define DH      96
#define INNER   768
#define SCALE_F 0.10206207261596577f   /* 96^-0.5 */
#define NEG_F   -1000000.0f
#define EPS_F   1e-5f

#define BM 128
#define BN 128
#define BK 16
#define TILE_W 2048
#define STAGES 3
#define KSPLIT 4
#define KCHUNK (M_PRO / KSPLIT)   /* 512 */

// ---------------- scratch (device globals; no allocations) ----------------
__device__ float g_q   [BATCH * N_PEP * INNER];
__device__ float g_k   [BATCH * M_PRO * INNER];
__device__ float g_vpT [BATCH * INNER * M_PRO];   // (b, d, m)
__device__ float g_vqT [BATCH * INNER * N_PEP];   // (b, d, n)
__device__ float g_cp  [BATCH * N_PEP * INNER];
__device__ float g_cq  [BATCH * M_PRO * INNER];
__device__ float g_y1  [BATCH * N_PEP * INNER];
__device__ float g_y2  [BATCH * M_PRO * INNER];
__device__ float g_part[KSPLIT * BATCH * N_PEP * INNER];

// ---------------- helpers ----------------
__device__ __forceinline__ void mma_tf32(float* c, const unsigned* a,
                                         unsigned b0, unsigned b1) {
    asm volatile(
        "mma.sync.aligned.m16n8k8.row.col.f32.tf32.tf32.f32 "
        "{%0,%1,%2,%3}, {%4,%5,%6,%7}, {%8,%9}, {%0,%1,%2,%3};"
        : "+f"(c[0]), "+f"(c[1]), "+f"(c[2]), "+f"(c[3])
        : "r"(a[0]), "r"(a[1]), "r"(a[2]), "r"(a[3]), "r"(b0), "r"(b1));
}

#define LDSM4(d, addr) \
    asm volatile("ldmatrix.sync.aligned.m8n8.x4.shared.b16 {%0,%1,%2,%3}, [%4];" \
        : "=r"((d)[0]), "=r"((d)[1]), "=r"((d)[2]), "=r"((d)[3]) : "r"(addr))

__device__ __forceinline__ void cpasync16(unsigned* dst, const float* src, bool pred) {
    unsigned sa = (unsigned)__cvta_generic_to_shared(dst);
    int sz = pred ? 16 : 0;
    asm volatile("cp.async.cg.shared.global [%0], [%1], 16, %2;\n"
                 :: "r"(sa), "l"(src), "r"(sz));
}
#define CP_COMMIT() asm volatile("cp.async.commit_group;\n" ::)
#define CP_WAIT1()  asm volatile("cp.async.wait_group 1;\n" ::)
#define CP_WAIT0()  asm volatile("cp.async.wait_group 0;\n" ::)

// swizzled word layouts, zero padding, conflict-free (LDS + LDSM verified):
#define SW16(r, c)  ((r) * 16  + ((c) ^ ((((r) >> 1) & 3) * 4)))
#define SW128(r, c) ((r) * 128 + ((c) ^ (((r) & 7) * 8)))

// ---------------- 128x128x16 3-stage-pipelined tf32 GEMM tile ----------------
// TA: A stored (K, M) row-major, lda; else (M, K).
// TB: B stored (N, K) row-major, ldb; else (K, N).
// MASK: apply attention masks in epilogue.
template <bool TA, bool TB, bool MASK>
__device__ __forceinline__ void gemm_mma(const float* __restrict__ A,
                                         const float* __restrict__ Bm,
                                         float* __restrict__ C,
                                         int M, int N, int K,
                                         int lda, int ldb, int ldc,
                                         float alpha, int row0, int col0,
                                         const int* __restrict__ rowmask,
                                         const int* __restrict__ colmask)
{
    __shared__ unsigned sAb[STAGES][TILE_W];
    __shared__ unsigned sBb[STAGES][TILE_W];

    const int tid  = threadIdx.x;
    const int lane = tid & 31;
    const int wid  = tid >> 5;
    const int wm   = (wid >> 1) * 32;
    const int wn   = (wid & 1) * 64;

    float acc[2][8][4];
#pragma unroll
    for (int i = 0; i < 2; i++)
#pragma unroll
        for (int j = 0; j < 8; j++)
#pragma unroll
            for (int t = 0; t < 4; t++) acc[i][j][t] = 0.0f;

    const int nTiles = K / BK;

    auto issue = [&](int buf, int k0) {
        unsigned* sA = sAb[buf];
        unsigned* sB = sBb[buf];
#pragma unroll
        for (int it = 0; it < 2; it++) {
            int idx = tid + it * 256;
            if (!TA) {
                int m  = idx >> 2;
                int kk = (idx & 3) * 4;
                cpasync16(&sA[SW16(m, kk)],
                          &A[(long)(row0 + m) * lda + k0 + kk], true);
            } else {
                int kk = idx >> 5;
                int m4 = (idx & 31) * 4;
                cpasync16(&sA[SW128(kk, m4)],
                          &A[(long)(k0 + kk) * lda + row0 + m4], true);
            }
        }
#pragma unroll
        for (int it = 0; it < 2; it++) {
            int idx = tid + it * 256;
            if (!TB) {
                int kk = idx >> 5;
                int n4 = (idx & 31) * 4;
                cpasync16(&sB[SW128(kk, n4)],
                          &Bm[(long)(k0 + kk) * ldb + col0 + n4],
                          col0 + n4 < N);
            } else {
                int n  = idx >> 2;
                int kq = (idx & 3) * 4;
                cpasync16(&sB[SW16(n, kq)],
                          &Bm[(long)(col0 + n) * ldb + k0 + kq],
                          col0 + n < N);
            }
        }
        CP_COMMIT();
    };

    const int arq = lane >> 2;
    const int ac  = lane & 3;

    // LDSM per-lane address components (SW16 layouts)
    const int a_rw  = wm + ((lane >> 3) & 1) * 8 + (lane & 7);
    const int a_kb4 = ((lane >> 4) & 1) * 4;
    const int a_sw  = ((a_rw >> 1) & 3) * 4;
    const int b_rw  = wn + ((lane >> 4) & 1) * 8 + (lane & 7);
    const int b_kb4 = ((lane >> 3) & 1) * 4;
    const int b_sw  = ((b_rw >> 1) & 3) * 4;

    issue(0, 0);
    if (nTiles > 1) issue(1, BK);

    for (int t = 0; t < nTiles; t++) {
        const int buf = t % STAGES;
        unsigned* sA = sAb[buf];
        unsigned* sB = sBb[buf];
        const uint32_t sAsh = (uint32_t)__cvta_generic_to_shared(sA);
        const uint32_t sBsh = (uint32_t)__cvta_generic_to_shared(sB);

        if (t + 1 < nTiles) CP_WAIT1(); else CP_WAIT0();
        __syncthreads();
        if (t + 2 < nTiles) issue((t + 2) % STAGES, (t + 2) * BK);

#pragma unroll
        for (int kc = 0; kc < BK; kc += 8) {
            unsigned af0[4], af1[4];
            if (!TA) {
                uint32_t a0 = sAsh + 4u * (a_rw * 16 + ((kc + a_kb4) ^ a_sw));
                LDSM4(af0, a0);
                LDSM4(af1, a0 + 1024);
            } else {
                af0[0] = sA[SW128(kc + ac,     wm + arq)];
                af0[1] = sA[SW128(kc + ac,     wm + arq + 8)];
                af0[2] = sA[SW128(kc + ac + 4, wm + arq)];
                af0[3] = sA[SW128(kc + ac + 4, wm + arq + 8)];
                af1[0] = sA[SW128(kc + ac,     wm + arq + 16)];
                af1[1] = sA[SW128(kc + ac,     wm + arq + 24)];
                af1[2] = sA[SW128(kc + ac + 4, wm + arq + 16)];
                af1[3] = sA[SW128(kc + ac + 4, wm + arq + 24)];
            }
            unsigned bf[4][4];
            if (TB) {
                uint32_t bb = sBsh + 4u * (b_rw * 16 + ((kc + b_kb4) ^ b_sw));
                LDSM4(bf[0], bb);
                LDSM4(bf[1], bb + 1024);
                LDSM4(bf[2], bb + 2048);
                LDSM4(bf[3], bb + 3072);
            }
#pragma unroll
            for (int j = 0; j < 8; j++) {
                unsigned b0, b1;
                if (TB) {
                    b0 = bf[j >> 1][(j & 1) * 2];
                    b1 = bf[j >> 1][(j & 1) * 2 + 1];
                } else {
                    const int bn = wn + j * 8 + arq;
                    b0 = sB[SW128(kc + ac,     bn)];
                    b1 = sB[SW128(kc + ac + 4, bn)];
                }
                mma_tf32(acc[0][j], af0, b0, b1);
                mma_tf32(acc[1][j], af1, b0, b1);
            }
        }
    }

    // ---- epilogue ----
#pragma unroll
    for (int i = 0; i < 2; i++) {
        int r  = row0 + wm + i * 16 + arq;
        int rv0 = 1, rv1 = 1;
        if (MASK) { rv0 = rowmask[r]; rv1 = rowmask[r + 8]; }
#pragma unroll
        for (int j = 0; j < 8; j++) {
            int c = col0 + wn + j * 8 + ac * 2;
            if (c < N) {
                float v0 = alpha * acc[i][j][0];
                float v1 = alpha * acc[i][j][1];
                float v2 = alpha * acc[i][j][2];
                float v3 = alpha * acc[i][j][3];
                if (MASK) {
                    int cm0 = colmask[c], cm1 = colmask[c + 1];
                    if (rv0 == 0 || cm0 == 0) v0 = NEG_F;
                    if (rv0 == 0 || cm1 == 0) v1 = NEG_F;
                    if (rv1 == 0 || cm0 == 0) v2 = NEG_F;
                    if (rv1 == 0 || cm1 == 0) v3 = NEG_F;
                }
                *(float2*)&C[(long)r * ldc + c]       = make_float2(v0, v1);
                *(float2*)&C[(long)(r + 8) * ldc + c] = make_float2(v2, v3);
            }
        }
    }
}

// ---------------- kernel wrappers ----------------
__global__ void __launch_bounds__(256, 2)
k_gemm_nn(const float* __restrict__ A, const float* __restrict__ Bm,
          float* __restrict__ C, int M, int N, int K,
          int lda, int ldb, int ldc, float alpha)
{
    gemm_mma<false, false, false>(A, Bm, C, M, N, K, lda, ldb, ldc, alpha,
                                  blockIdx.y * BM, blockIdx.x * BN, 0, 0);
}

// XT projection: CT[z] (INNER, tokens) = W^T @ X[z]^T ; TA=1 (A=W natural), TB=1 (B=X natural)
__global__ void __launch_bounds__(256, 2)
k_projT(const float* __restrict__ W, const float* __restrict__ X,
        float* __restrict__ CT, int tokens)
{
    int z = blockIdx.z;
    gemm_mma<true, true, false>(W, X + (long)z * tokens * INNER,
                                CT + (long)z * INNER * tokens,
                                INNER, tokens, INNER,
                                INNER, INNER, tokens, 1.0f,
                                blockIdx.y * BM, blockIdx.x * BN, 0, 0);
}

// scores with fused masking
__global__ void __launch_bounds__(256, 2)
k_scores(const float* __restrict__ q, const float* __restrict__ kb,
         float* __restrict__ attn,
         const int* __restrict__ pmask, const int* __restrict__ promask)
{
    int z = blockIdx.z;
    int b = z >> 3, h = z & 7;
    const float* A  = q  + (long)b * N_PEP * INNER + h * DH;
    const float* Bm = kb + (long)b * M_PRO * INNER + h * DH;
    float* C = attn + (long)z * N_PEP * M_PRO;
    gemm_mma<false, true, true>(A, Bm, C, N_PEP, M_PRO, DH,
                                INNER, INNER, M_PRO, SCALE_F,
                                blockIdx.y * BM, blockIdx.x * BN,
                                pmask + b * N_PEP, promask + b * M_PRO);
}

// split-K ctx_prot: B = vpT (d, m), TB=1
__global__ void __launch_bounds__(256, 2)
k_ctxprot(const float* __restrict__ attn, const float* __restrict__ vpT,
          float* __restrict__ part)
{
    int z = blockIdx.z;
    int bh = z >> 2, chunk = z & 3;
    int b = bh >> 3, h = bh & 7;
    const float* A  = attn + (long)bh * N_PEP * M_PRO + chunk * KCHUNK;
    const float* Bm = vpT + (long)b * INNER * M_PRO + (long)h * DH * M_PRO + chunk * KCHUNK;
    float* C = part + (long)chunk * (BATCH * N_PEP * INNER)
                    + (long)b * N_PEP * INNER + h * DH;
    gemm_mma<false, true, false>(A, Bm, C, N_PEP, DH, KCHUNK,
                                 M_PRO, M_PRO, INNER, 1.0f, 0, 0, 0, 0);
}

// reduce 4 partials -> cp
__global__ void __launch_bounds__(256)
k_reduce4(const float* __restrict__ part, float* __restrict__ cp)
{
    const long STRIDE = (long)BATCH * N_PEP * INNER;
    long i = ((long)blockIdx.x * 256 + threadIdx.x) * 4;
    if (i >= STRIDE) return;
    float4 a = *(const float4*)&part[i];
    float4 b = *(const float4*)&part[STRIDE + i];
    float4 c = *(const float4*)&part[2 * STRIDE + i];
    float4 d = *(const float4*)&part[3 * STRIDE + i];
    *(float4*)&cp[i] = make_float4(a.x + b.x + c.x + d.x, a.y + b.y + c.y + d.y,
                                   a.z + b.z + c.z + d.z, a.w + b.w + c.w + d.w);
}

// ctx_pep: A = attn^T (TA=1), B = vqT (d, n) TB=1
__global__ void __launch_bounds__(256, 2)
k_ctxpep(const float* __restrict__ attn, const float* __restrict__ vqT,
         float* __restrict__ ctx)
{
    int z = blockIdx.z; int b = z >> 3, h = z & 7;
    const float* A  = attn + (long)z * N_PEP * M_PRO;
    const float* Bm = vqT + (long)b * INNER * N_PEP + (long)h * DH * N_PEP;
    float* C = ctx + (long)b * M_PRO * INNER + h * DH;
    gemm_mma<true, true, false>(A, Bm, C, M_PRO, DH, N_PEP,
                                M_PRO, N_PEP, INNER, 1.0f,
                                blockIdx.y * BM, 0, 0, 0);
}

// ---------------- softmax (masks pre-applied as NEG_F) ----------------
__global__ void __launch_bounds__(256)
k_softmax(float* __restrict__ attn)
{
    const int tid = threadIdx.x;
    float* p = attn + (long)blockIdx.x * M_PRO;

    float4 v0 = *(float4*)&p[tid * 4];
    float4 v1 = *(float4*)&p[1024 + tid * 4];

    float mx = fmaxf(fmaxf(fmaxf(v0.x, v0.y), fmaxf(v0.z, v0.w)),
                     fmaxf(fmaxf(v1.x, v1.y), fmaxf(v1.z, v1.w)));
#pragma unroll
    for (int o = 16; o; o >>= 1)
        mx = fmaxf(mx, __shfl_xor_sync(0xffffffff, mx, o));
    __shared__ float red[8];
    if ((tid & 31) == 0) red[tid >> 5] = mx;
    __syncthreads();
    if (tid < 8) {
        float m = red[tid];
#pragma unroll
        for (int o = 4; o; o >>= 1) m = fmaxf(m, __shfl_xor_sync(0xff, m, o));
        red[tid] = m;
    }
    __syncthreads();
    mx = red[0];

    v0.x = expf(v0.x - mx); v0.y = expf(v0.y - mx);
    v0.z = expf(v0.z - mx); v0.w = expf(v0.w - mx);
    v1.x = expf(v1.x - mx); v1.y = expf(v1.y - mx);
    v1.z = expf(v1.z - mx); v1.w = expf(v1.w - mx);
    float s = v0.x + v0.y + v0.z + v0.w + v1.x + v1.y + v1.z + v1.w;
#pragma unroll
    for (int o = 16; o; o >>= 1) s += __shfl_xor_sync(0xffffffff, s, o);
    __shared__ float red2[8];
    if ((tid & 31) == 0) red2[tid >> 5] = s;
    __syncthreads();
    if (tid < 8) {
        float t = red2[tid];
#pragma unroll
        for (int o = 4; o; o >>= 1) t += __shfl_xor_sync(0xff, t, o);
        red2[tid] = t;
    }
    __syncthreads();
    float inv = 1.0f / red2[0];

    v0.x *= inv; v0.y *= inv; v0.z *= inv; v0.w *= inv;
    v1.x *= inv; v1.y *= inv; v1.z *= inv; v1.w *= inv;
    *(float4*)&p[tid * 4] = v0;
    *(float4*)&p[1024 + tid * 4] = v1;
}

// ---------------- out = LayerNorm(Y + bias + residual) * g + b ----------------
__global__ void __launch_bounds__(256)
k_ln(const float* __restrict__ Y, const float* __restrict__ bo,
     const float* __restrict__ resid, const float* __restrict__ g,
     const float* __restrict__ beta, float* __restrict__ out)
{
    int row = blockIdx.x;
    int tid = threadIdx.x;
    const float* y = Y + (long)row * INNER;
    const float* r = resid + (long)row * INNER;

    float x[3];
    float s = 0.0f;
#pragma unroll
    for (int i = 0; i < 3; i++) {
        int c = tid + i * 256;
        x[i] = y[c] + bo[c] + r[c];
        s += x[i];
    }
#pragma unroll
    for (int o = 16; o; o >>= 1) s += __shfl_xor_sync(0xffffffff, s, o);
    __shared__ float red[8];
    if ((tid & 31) == 0) red[tid >> 5] = s;
    __syncthreads();
    if (tid < 8) {
        float t = red[tid];
#pragma unroll
        for (int o = 4; o; o >>= 1) t += __shfl_xor_sync(0xff, t, o);
        red[tid] = t;
    }
    __syncthreads();
    float mu = red[0] * (1.0f / INNER);

    float v = 0.0f;
#pragma unroll
    for (int i = 0; i < 3; i++) { float d = x[i] - mu; v += d * d; }
#pragma unroll
    for (int o = 16; o; o >>= 1) v += __shfl_xor_sync(0xffffffff, v, o);
    __shared__ float red2[8];
    if ((tid & 31) == 0) red2[tid >> 5] = v;
    __syncthreads();
    if (tid < 8) {
        float t = red2[tid];
#pragma unroll
        for (int o = 4; o; o >>= 1) t += __shfl_xor_sync(0xff, t, o);
        red2[tid] = t;
    }
    __syncthreads();
    float rstd = rsqrtf(red2[0] * (1.0f / INNER) + EPS_F);
#pragma unroll
    for (int i = 0; i < 3; i++) {
        int c = tid + i * 256;
        out[(long)row * INNER + c] = (x[i] - mu) * rstd * g[c] + beta[c];
    }
}

// ---------------- launch ----------------
extern "C" void kernel_launch(void* const* d_in, const int* in_sizes, int n_in,
                              void* d_out, int out_size)
{
    const float* peptide = (const float*)d_in[0];
    const float* protein = (const float*)d_in[1];
    const int*   pmask   = (const int*)  d_in[2];
    const int*   promask = (const int*)  d_in[3];
    const float* Wq      = (const float*)d_in[4];
    const float* Wk      = (const float*)d_in[5];
    const float* Wvp     = (const float*)d_in[6];
    const float* Wvq     = (const float*)d_in[7];
    const float* Wop     = (const float*)d_in[8];
    const float* bop     = (const float*)d_in[9];
    const float* Woq     = (const float*)d_in[10];
    const float* boq     = (const float*)d_in[11];
    const float* lng     = (const float*)d_in[12];
    const float* lnb     = (const float*)d_in[13];

    float* out = (float*)d_out;
    float* out_prot = out;                                   // (16,128,768)
    float* out_pep  = out + (long)BATCH * N_PEP * INNER;     // (16,2048,768)
    float* attn     = out_pep + (long)BATCH * M_PRO * INNER; // (16,8,128,2048)

    float *q, *k, *vpT, *vqT, *cp, *cq, *y1, *y2, *part;
    cudaGetSymbolAddress((void**)&q,   g_q);
    cudaGetSymbolAddress((void**)&k,   g_k);
    cudaGetSymbolAddress((void**)&vpT, g_vpT);
    cudaGetSymbolAddress((void**)&vqT, g_vqT);
    cudaGetSymbolAddress((void**)&cp,  g_cp);
    cudaGetSymbolAddress((void**)&cq,  g_cq);
    cudaGetSymbolAddress((void**)&y1,  g_y1);
    cudaGetSymbolAddress((void**)&y2,  g_y2);
    cudaGetSymbolAddress((void**)&part, g_part);

    const dim3 blk(256);

    // projections
    k_gemm_nn<<<dim3(6, 16),  blk>>>(peptide, Wq, q, BATCH * N_PEP, INNER, INNER, INNER, INNER, INNER, 1.0f);
    k_gemm_nn<<<dim3(6, 256), blk>>>(protein, Wk, k, BATCH * M_PRO, INNER, INNER, INNER, INNER, INNER, 1.0f);
    k_projT<<<dim3(16, 6, BATCH), blk>>>(Wvp, protein, vpT, M_PRO);
    k_projT<<<dim3(1,  6, BATCH), blk>>>(Wvq, peptide, vqT, N_PEP);

    // attention scores (mask fused) + softmax (attn lives in d_out)
    k_scores <<<dim3(16, 1, BATCH * HEADS), blk>>>(q, k, attn, pmask, promask);
    k_softmax<<<BATCH * HEADS * N_PEP, 256>>>(attn);

    // context
    k_ctxprot<<<dim3(1, 1, BATCH * HEADS * KSPLIT), blk>>>(attn, vpT, part);
    k_reduce4<<<(BATCH * N_PEP * INNER / 4 + 255) / 256, blk>>>(part, cp);
    k_ctxpep <<<dim3(1, 16, BATCH * HEADS), blk>>>(attn, vqT, cq);

    // output projections
    k_gemm_nn<<<dim3(6, 16),  blk>>>(cp, Wop, y1, BATCH * N_PEP, INNER, INNER, INNER, INNER, INNER, 1.0f);
    k_gemm_nn<<<dim3(6, 256), blk>>>(cq, Woq, y2, BATCH * M_PRO, INNER, INNER, INNER, INNER, INNER, 1.0f);

    // bias + residual + layernorm
    k_ln<<<BATCH * N_PEP, 256>>>(y1, bop, peptide, lng, lnb, out_prot);
    k_ln<<<BATCH * M_PRO, 256>>>(y2, boq, protein, lng, lnb, out_pep);
}

// round 11
// speedup vs baseline: 1.4992x; 1.4992x over previous
#include <cuda_runtime.h>
#include <math.h>

#define BATCH   16
#define N_PEP   128
#define M_PRO   2048
#define HEADS   8
#define DH      96
#define INNER   768
#define SCALE_F 0.10206207261596577f   /* 96^-0.5 */
#define NEG_F   -1000000.0f
#define EPS_F   1e-5f

#define BM 128
#define BN 128
#define BK 16
#define TILE_W 2048
#define STAGES 3
#define KSPLIT 4
#define KCHUNK (M_PRO / KSPLIT)   /* 512 */

// ---------------- scratch (device globals; no allocations) ----------------
__device__ float g_q   [BATCH * N_PEP * INNER];
__device__ float g_k   [BATCH * M_PRO * INNER];
__device__ float g_vp  [BATCH * M_PRO * INNER];
__device__ float g_vq  [BATCH * N_PEP * INNER];
__device__ float g_cp  [BATCH * N_PEP * INNER];
__device__ float g_cq  [BATCH * M_PRO * INNER];
__device__ float g_y1  [BATCH * N_PEP * INNER];
__device__ float g_y2  [BATCH * M_PRO * INNER];
__device__ float g_part[KSPLIT * BATCH * N_PEP * INNER];

// ---------------- helpers ----------------
__device__ __forceinline__ void mma_tf32(float* c, const unsigned* a,
                                         unsigned b0, unsigned b1) {
    asm volatile(
        "mma.sync.aligned.m16n8k8.row.col.f32.tf32.tf32.f32 "
        "{%0,%1,%2,%3}, {%4,%5,%6,%7}, {%8,%9}, {%0,%1,%2,%3};"
        : "+f"(c[0]), "+f"(c[1]), "+f"(c[2]), "+f"(c[3])
        : "r"(a[0]), "r"(a[1]), "r"(a[2]), "r"(a[3]), "r"(b0), "r"(b1));
}

__device__ __forceinline__ void cpasync16(unsigned* dst, const float* src, bool pred) {
    unsigned sa = (unsigned)__cvta_generic_to_shared(dst);
    int sz = pred ? 16 : 0;
    asm volatile("cp.async.cg.shared.global [%0], [%1], 16, %2;\n"
                 :: "r"(sa), "l"(src), "r"(sz));
}
#define CP_COMMIT() asm volatile("cp.async.commit_group;\n" ::)
#define CP_WAIT1()  asm volatile("cp.async.wait_group 1;\n" ::)
#define CP_WAIT0()  asm volatile("cp.async.wait_group 0;\n" ::)

// swizzled word layouts, zero padding, all accesses conflict-free:
#define SW16(r, c)  ((r) * 16  + ((c) ^ ((((r) >> 1) & 3) * 4)))
#define SW128(r, c) ((r) * 128 + ((c) ^ (((r) & 7) * 8)))

// ---------------- 128x128x16 3-stage-pipelined tf32 GEMM tile ----------------
// Raw fp32 bits fed to mma.sync.tf32 (HW truncates).
// TA: A stored (K, M) row-major, lda; else (M, K).
// TB: B stored (N, K) row-major, ldb; else (K, N).
// MASK: apply attention masks in epilogue.
template <bool TA, bool TB, bool MASK>
__device__ __forceinline__ void gemm_mma(const float* __restrict__ A,
                                         const float* __restrict__ Bm,
                                         float* __restrict__ C,
                                         int M, int N, int K,
                                         int lda, int ldb, int ldc,
                                         float alpha, int row0, int col0,
                                         const int* __restrict__ rowmask,
                                         const int* __restrict__ colmask)
{
    __shared__ unsigned sAb[STAGES][TILE_W];
    __shared__ unsigned sBb[STAGES][TILE_W];

    const int tid  = threadIdx.x;
    const int lane = tid & 31;
    const int wid  = tid >> 5;
    const int wm   = (wid >> 1) * 32;
    const int wn   = (wid & 1) * 64;

    float acc[2][8][4];
#pragma unroll
    for (int i = 0; i < 2; i++)
#pragma unroll
        for (int j = 0; j < 8; j++)
#pragma unroll
            for (int t = 0; t < 4; t++) acc[i][j][t] = 0.0f;

    const int nTiles = K / BK;

    auto issue = [&](int buf, int k0) {
        unsigned* sA = sAb[buf];
        unsigned* sB = sBb[buf];
#pragma unroll
        for (int it = 0; it < 2; it++) {
            int idx = tid + it * 256;
            if (!TA) {
                int m  = idx >> 2;
                int kk = (idx & 3) * 4;
                cpasync16(&sA[SW16(m, kk)],
                          &A[(long)(row0 + m) * lda + k0 + kk], true);
            } else {
                int kk = idx >> 5;
                int m4 = (idx & 31) * 4;
                cpasync16(&sA[SW128(kk, m4)],
                          &A[(long)(k0 + kk) * lda + row0 + m4], true);
            }
        }
#pragma unroll
        for (int it = 0; it < 2; it++) {
            int idx = tid + it * 256;
            if (!TB) {
                int kk = idx >> 5;
                int n4 = (idx & 31) * 4;
                cpasync16(&sB[SW128(kk, n4)],
                          &Bm[(long)(k0 + kk) * ldb + col0 + n4],
                          col0 + n4 < N);
            } else {
                int n  = idx >> 2;
                int kq = (idx & 3) * 4;
                cpasync16(&sB[SW16(n, kq)],
                          &Bm[(long)(col0 + n) * ldb + k0 + kq],
                          col0 + n < N);
            }
        }
        CP_COMMIT();
    };

    const int arq = lane >> 2;
    const int ac  = lane & 3;

    issue(0, 0);
    if (nTiles > 1) issue(1, BK);

    for (int t = 0; t < nTiles; t++) {
        const int buf = t % STAGES;
        unsigned* sA = sAb[buf];
        unsigned* sB = sBb[buf];

        if (t + 1 < nTiles) CP_WAIT1(); else CP_WAIT0();
        __syncthreads();
        if (t + 2 < nTiles) issue((t + 2) % STAGES, (t + 2) * BK);

#pragma unroll
        for (int kc = 0; kc < BK; kc += 8) {
            unsigned af0[4], af1[4];
            if (!TA) {
                af0[0] = sA[SW16(wm + arq,      kc + ac)];
                af0[1] = sA[SW16(wm + arq + 8,  kc + ac)];
                af0[2] = sA[SW16(wm + arq,      kc + ac + 4)];
                af0[3] = sA[SW16(wm + arq + 8,  kc + ac + 4)];
                af1[0] = sA[SW16(wm + arq + 16, kc + ac)];
                af1[1] = sA[SW16(wm + arq + 24, kc + ac)];
                af1[2] = sA[SW16(wm + arq + 16, kc + ac + 4)];
                af1[3] = sA[SW16(wm + arq + 24, kc + ac + 4)];
            } else {
                af0[0] = sA[SW128(kc + ac,     wm + arq)];
                af0[1] = sA[SW128(kc + ac,     wm + arq + 8)];
                af0[2] = sA[SW128(kc + ac + 4, wm + arq)];
                af0[3] = sA[SW128(kc + ac + 4, wm + arq + 8)];
                af1[0] = sA[SW128(kc + ac,     wm + arq + 16)];
                af1[1] = sA[SW128(kc + ac,     wm + arq + 24)];
                af1[2] = sA[SW128(kc + ac + 4, wm + arq + 16)];
                af1[3] = sA[SW128(kc + ac + 4, wm + arq + 24)];
            }
#pragma unroll
            for (int j = 0; j < 8; j++) {
                const int bn = wn + j * 8 + arq;
                unsigned b0, b1;
                if (!TB) {
                    b0 = sB[SW128(kc + ac,     bn)];
                    b1 = sB[SW128(kc + ac + 4, bn)];
                } else {
                    b0 = sB[SW16(bn, kc + ac)];
                    b1 = sB[SW16(bn, kc + ac + 4)];
                }
                mma_tf32(acc[0][j], af0, b0, b1);
                mma_tf32(acc[1][j], af1, b0, b1);
            }
        }
    }

    // ---- epilogue ----
#pragma unroll
    for (int i = 0; i < 2; i++) {
        int r  = row0 + wm + i * 16 + arq;
        int rv0 = 1, rv1 = 1;
        if (MASK) { rv0 = rowmask[r]; rv1 = rowmask[r + 8]; }
#pragma unroll
        for (int j = 0; j < 8; j++) {
            int c = col0 + wn + j * 8 + ac * 2;
            if (c < N) {
                float v0 = alpha * acc[i][j][0];
                float v1 = alpha * acc[i][j][1];
                float v2 = alpha * acc[i][j][2];
                float v3 = alpha * acc[i][j][3];
                if (MASK) {
                    int cm0 = colmask[c], cm1 = colmask[c + 1];
                    if (rv0 == 0 || cm0 == 0) v0 = NEG_F;
                    if (rv0 == 0 || cm1 == 0) v1 = NEG_F;
                    if (rv1 == 0 || cm0 == 0) v2 = NEG_F;
                    if (rv1 == 0 || cm1 == 0) v3 = NEG_F;
                }
                *(float2*)&C[(long)r * ldc + c]       = make_float2(v0, v1);
                *(float2*)&C[(long)(r + 8) * ldc + c] = make_float2(v2, v3);
            }
        }
    }
}

// ---------------- kernel wrappers ----------------
__global__ void __launch_bounds__(256, 2)
k_gemm_nn(const float* __restrict__ A, const float* __restrict__ Bm,
          float* __restrict__ C, int M, int N, int K,
          int lda, int ldb, int ldc, float alpha)
{
    gemm_mma<false, false, false>(A, Bm, C, M, N, K, lda, ldb, ldc, alpha,
                                  blockIdx.y * BM, blockIdx.x * BN, 0, 0);
}

// fused peptide projections: z=0 -> Wq->q, z=1 -> Wvq->vq
__global__ void __launch_bounds__(256, 2)
k_proj_pep(const float* __restrict__ pep,
           const float* __restrict__ Wq, const float* __restrict__ Wvq,
           float* __restrict__ q, float* __restrict__ vq)
{
    const float* Bm = blockIdx.z ? Wvq : Wq;
    float* C = blockIdx.z ? vq : q;
    gemm_mma<false, false, false>(pep, Bm, C, BATCH * N_PEP, INNER, INNER,
                                  INNER, INNER, INNER, 1.0f,
                                  blockIdx.y * BM, blockIdx.x * BN, 0, 0);
}

// fused output projections: by<256 -> y2 (cq@Woq), else -> y1 (cp@Wop)
__global__ void __launch_bounds__(256, 2)
k_out_dual(const float* __restrict__ cq, const float* __restrict__ Woq,
           float* __restrict__ y2,
           const float* __restrict__ cp, const float* __restrict__ Wop,
           float* __restrict__ y1)
{
    if (blockIdx.y < 256) {
        gemm_mma<false, false, false>(cq, Woq, y2, BATCH * M_PRO, INNER, INNER,
                                      INNER, INNER, INNER, 1.0f,
                                      blockIdx.y * BM, blockIdx.x * BN, 0, 0);
    } else {
        gemm_mma<false, false, false>(cp, Wop, y1, BATCH * N_PEP, INNER, INNER,
                                      INNER, INNER, INNER, 1.0f,
                                      (blockIdx.y - 256) * BM, blockIdx.x * BN, 0, 0);
    }
}

// scores with fused masking: writes NEG_F where masked
__global__ void __launch_bounds__(256, 2)
k_scores(const float* __restrict__ q, const float* __restrict__ kb,
         float* __restrict__ attn,
         const int* __restrict__ pmask, const int* __restrict__ promask)
{
    int z = blockIdx.z;
    int b = z >> 3, h = z & 7;
    const float* A  = q  + (long)b * N_PEP * INNER + h * DH;
    const float* Bm = kb + (long)b * M_PRO * INNER + h * DH;
    float* C = attn + (long)z * N_PEP * M_PRO;
    gemm_mma<false, true, true>(A, Bm, C, N_PEP, M_PRO, DH,
                                INNER, INNER, M_PRO, SCALE_F,
                                blockIdx.y * BM, blockIdx.x * BN,
                                pmask + b * N_PEP, promask + b * M_PRO);
}

// split-K ctx_prot
__global__ void __launch_bounds__(256, 2)
k_ctxprot(const float* __restrict__ attn, const float* __restrict__ vprot,
          float* __restrict__ part)
{
    int z = blockIdx.z;
    int bh = z >> 2, chunk = z & 3;
    int b = bh >> 3, h = bh & 7;
    const float* A  = attn  + (long)bh * N_PEP * M_PRO + chunk * KCHUNK;
    const float* Bm = vprot + (long)b * M_PRO * INNER + (long)chunk * KCHUNK * INNER + h * DH;
    float* C = part + (long)chunk * (BATCH * N_PEP * INNER)
                    + (long)b * N_PEP * INNER + h * DH;
    gemm_mma<false, false, false>(A, Bm, C, N_PEP, DH, KCHUNK,
                                  M_PRO, INNER, INNER, 1.0f, 0, 0, 0, 0);
}

// reduce 4 partials -> cp
__global__ void __launch_bounds__(256)
k_reduce4(const float* __restrict__ part, float* __restrict__ cp)
{
    const long STRIDE = (long)BATCH * N_PEP * INNER;
    long i = ((long)blockIdx.x * 256 + threadIdx.x) * 4;
    if (i >= STRIDE) return;
    float4 a = *(const float4*)&part[i];
    float4 b = *(const float4*)&part[STRIDE + i];
    float4 c = *(const float4*)&part[2 * STRIDE + i];
    float4 d = *(const float4*)&part[3 * STRIDE + i];
    *(float4*)&cp[i] = make_float4(a.x + b.x + c.x + d.x, a.y + b.y + c.y + d.y,
                                   a.z + b.z + c.z + d.z, a.w + b.w + c.w + d.w);
}

__global__ void __launch_bounds__(256, 2)
k_ctxpep(const float* __restrict__ attn, const float* __restrict__ vpep,
         float* __restrict__ ctx)
{
    int z = blockIdx.z; int b = z >> 3, h = z & 7;
    const float* A  = attn + (long)z * N_PEP * M_PRO;
    const float* Bm = vpep + (long)b * N_PEP * INNER + h * DH;
    float* C = ctx + (long)b * M_PRO * INNER + h * DH;
    gemm_mma<true, false, false>(A, Bm, C, M_PRO, DH, N_PEP,
                                 M_PRO, INNER, INNER, 1.0f,
                                 blockIdx.y * BM, 0, 0, 0);
}

// ---------------- softmax (masks pre-applied as NEG_F) ----------------
__global__ void __launch_bounds__(256)
k_softmax(float* __restrict__ attn)
{
    const int tid = threadIdx.x;
    float* p = attn + (long)blockIdx.x * M_PRO;

    float4 v0 = *(float4*)&p[tid * 4];
    float4 v1 = *(float4*)&p[1024 + tid * 4];

    float mx = fmaxf(fmaxf(fmaxf(v0.x, v0.y), fmaxf(v0.z, v0.w)),
                     fmaxf(fmaxf(v1.x, v1.y), fmaxf(v1.z, v1.w)));
#pragma unroll
    for (int o = 16; o; o >>= 1)
        mx = fmaxf(mx, __shfl_xor_sync(0xffffffff, mx, o));
    __shared__ float red[8];
    if ((tid & 31) == 0) red[tid >> 5] = mx;
    __syncthreads();
    if (tid < 8) {
        float m = red[tid];
#pragma unroll
        for (int o = 4; o; o >>= 1) m = fmaxf(m, __shfl_xor_sync(0xff, m, o));
        red[tid] = m;
    }
    __syncthreads();
    mx = red[0];

    v0.x = expf(v0.x - mx); v0.y = expf(v0.y - mx);
    v0.z = expf(v0.z - mx); v0.w = expf(v0.w - mx);
    v1.x = expf(v1.x - mx); v1.y = expf(v1.y - mx);
    v1.z = expf(v1.z - mx); v1.w = expf(v1.w - mx);
    float s = v0.x + v0.y + v0.z + v0.w + v1.x + v1.y + v1.z + v1.w;
#pragma unroll
    for (int o = 16; o; o >>= 1) s += __shfl_xor_sync(0xffffffff, s, o);
    __shared__ float red2[8];
    if ((tid & 31) == 0) red2[tid >> 5] = s;
    __syncthreads();
    if (tid < 8) {
        float t = red2[tid];
#pragma unroll
        for (int o = 4; o; o >>= 1) t += __shfl_xor_sync(0xff, t, o);
        red2[tid] = t;
    }
    __syncthreads();
    float inv = 1.0f / red2[0];

    v0.x *= inv; v0.y *= inv; v0.z *= inv; v0.w *= inv;
    v1.x *= inv; v1.y *= inv; v1.z *= inv; v1.w *= inv;
    *(float4*)&p[tid * 4] = v0;
    *(float4*)&p[1024 + tid * 4] = v1;
}

// ---------------- fused LN: rows < 2048 -> (y1,pep,out_prot), else (y2,prot,out_pep) ----------------
__global__ void __launch_bounds__(256)
k_ln_dual(const float* __restrict__ y1, const float* __restrict__ bo1,
          const float* __restrict__ res1, float* __restrict__ out1,
          const float* __restrict__ y2, const float* __restrict__ bo2,
          const float* __restrict__ res2, float* __restrict__ out2,
          const float* __restrict__ g, const float* __restrict__ beta)
{
    const int NROW1 = BATCH * N_PEP;   // 2048
    int row = blockIdx.x;
    const float *y, *bo, *r; float* out; int lrow;
    if (row < NROW1) { y = y1; bo = bo1; r = res1; out = out1; lrow = row; }
    else             { y = y2; bo = bo2; r = res2; out = out2; lrow = row - NROW1; }
    int tid = threadIdx.x;
    const float* yp = y + (long)lrow * INNER;
    const float* rp = r + (long)lrow * INNER;

    float x[3];
    float s = 0.0f;
#pragma unroll
    for (int i = 0; i < 3; i++) {
        int c = tid + i * 256;
        x[i] = yp[c] + bo[c] + rp[c];
        s += x[i];
    }
#pragma unroll
    for (int o = 16; o; o >>= 1) s += __shfl_xor_sync(0xffffffff, s, o);
    __shared__ float red[8];
    if ((tid & 31) == 0) red[tid >> 5] = s;
    __syncthreads();
    if (tid < 8) {
        float t = red[tid];
#pragma unroll
        for (int o = 4; o; o >>= 1) t += __shfl_xor_sync(0xff, t, o);
        red[tid] = t;
    }
    __syncthreads();
    float mu = red[0] * (1.0f / INNER);

    float v = 0.0f;
#pragma unroll
    for (int i = 0; i < 3; i++) { float d = x[i] - mu; v += d * d; }
#pragma unroll
    for (int o = 16; o; o >>= 1) v += __shfl_xor_sync(0xffffffff, v, o);
    __shared__ float red2[8];
    if ((tid & 31) == 0) red2[tid >> 5] = v;
    __syncthreads();
    if (tid < 8) {
        float t = red2[tid];
#pragma unroll
        for (int o = 4; o; o >>= 1) t += __shfl_xor_sync(0xff, t, o);
        red2[tid] = t;
    }
    __syncthreads();
    float rstd = rsqrtf(red2[0] * (1.0f / INNER) + EPS_F);
#pragma unroll
    for (int i = 0; i < 3; i++) {
        int c = tid + i * 256;
        out[(long)lrow * INNER + c] = (x[i] - mu) * rstd * g[c] + beta[c];
    }
}

// ---------------- launch ----------------
extern "C" void kernel_launch(void* const* d_in, const int* in_sizes, int n_in,
                              void* d_out, int out_size)
{
    const float* peptide = (const float*)d_in[0];
    const float* protein = (const float*)d_in[1];
    const int*   pmask   = (const int*)  d_in[2];
    const int*   promask = (const int*)  d_in[3];
    const float* Wq      = (const float*)d_in[4];
    const float* Wk      = (const float*)d_in[5];
    const float* Wvp     = (const float*)d_in[6];
    const float* Wvq     = (const float*)d_in[7];
    const float* Wop     = (const float*)d_in[8];
    const float* bop     = (const float*)d_in[9];
    const float* Woq     = (const float*)d_in[10];
    const float* boq     = (const float*)d_in[11];
    const float* lng     = (const float*)d_in[12];
    const float* lnb     = (const float*)d_in[13];

    float* out = (float*)d_out;
    float* out_prot = out;                                   // (16,128,768)
    float* out_pep  = out + (long)BATCH * N_PEP * INNER;     // (16,2048,768)
    float* attn     = out_pep + (long)BATCH * M_PRO * INNER; // (16,8,128,2048)

    float *q, *k, *vp, *vq, *cp, *cq, *y1, *y2, *part;
    cudaGetSymbolAddress((void**)&q,  g_q);
    cudaGetSymbolAddress((void**)&k,  g_k);
    cudaGetSymbolAddress((void**)&vp, g_vp);
    cudaGetSymbolAddress((void**)&vq, g_vq);
    cudaGetSymbolAddress((void**)&cp, g_cp);
    cudaGetSymbolAddress((void**)&cq, g_cq);
    cudaGetSymbolAddress((void**)&y1, g_y1);
    cudaGetSymbolAddress((void**)&y2, g_y2);
    cudaGetSymbolAddress((void**)&part, g_part);

    const dim3 blk(256);

    // projections (peptide pair fused into one launch)
    k_proj_pep<<<dim3(6, 16, 2), blk>>>(peptide, Wq, Wvq, q, vq);
    k_gemm_nn<<<dim3(6, 256), blk>>>(protein, Wk,  k,  BATCH * M_PRO, INNER, INNER, INNER, INNER, INNER, 1.0f);
    k_gemm_nn<<<dim3(6, 256), blk>>>(protein, Wvp, vp, BATCH * M_PRO, INNER, INNER, INNER, INNER, INNER, 1.0f);

    // attention scores (mask fused) + softmax (attn lives in d_out)
    k_scores <<<dim3(16, 1, BATCH * HEADS), blk>>>(q, k, attn, pmask, promask);
    k_softmax<<<BATCH * HEADS * N_PEP, 256>>>(attn);

    // context
    k_ctxprot<<<dim3(1, 1, BATCH * HEADS * KSPLIT), blk>>>(attn, vp, part);
    k_reduce4<<<(BATCH * N_PEP * INNER / 4 + 255) / 256, blk>>>(part, cp);
    k_ctxpep <<<dim3(1, 16, BATCH * HEADS), blk>>>(attn, vq, cq);

    // output projections (y2 + y1 fused into one launch)
    k_out_dual<<<dim3(6, 272), blk>>>(cq, Woq, y2, cp, Wop, y1);

    // bias + residual + layernorm (fused)
    k_ln_dual<<<BATCH * N_PEP + BATCH * M_PRO, 256>>>(
        y1, bop, peptide, out_prot, y2, boq, protein, out_pep, lng, lnb);
}

// round 12
// speedup vs baseline: 1.5753x; 1.0507x over previous
#include <cuda_runtime.h>
#include <math.h>

#define BATCH   16
#define N_PEP   128
#define M_PRO   2048
#define HEADS   8
#define DH      96
#define INNER   768
#define SCALE_F 0.10206207261596577f   /* 96^-0.5 */
#define NEG_F   -1000000.0f
#define EPS_F   1e-5f

#define BM 128
#define BN 128
#define BK 16
#define TILE_W 2048
#define STAGES 3
#define KSPLIT 4
#define KCHUNK (M_PRO / KSPLIT)   /* 512 */

// ---------------- scratch (device globals; no allocations) ----------------
__device__ float g_q   [BATCH * N_PEP * INNER];
__device__ float g_k   [BATCH * M_PRO * INNER];
__device__ float g_vp  [BATCH * M_PRO * INNER];
__device__ float g_vq  [BATCH * N_PEP * INNER];
__device__ float g_cp  [BATCH * N_PEP * INNER];
__device__ float g_cq  [BATCH * M_PRO * INNER];
__device__ float g_y1  [BATCH * N_PEP * INNER];
__device__ float g_y2  [BATCH * M_PRO * INNER];
__device__ float g_part[KSPLIT * BATCH * N_PEP * INNER];

// ---------------- helpers ----------------
__device__ __forceinline__ void mma_tf32(float* c, const unsigned* a,
                                         unsigned b0, unsigned b1) {
    asm volatile(
        "mma.sync.aligned.m16n8k8.row.col.f32.tf32.tf32.f32 "
        "{%0,%1,%2,%3}, {%4,%5,%6,%7}, {%8,%9}, {%0,%1,%2,%3};"
        : "+f"(c[0]), "+f"(c[1]), "+f"(c[2]), "+f"(c[3])
        : "r"(a[0]), "r"(a[1]), "r"(a[2]), "r"(a[3]), "r"(b0), "r"(b1));
}

__device__ __forceinline__ void cpasync16(unsigned* dst, const float* src, bool pred) {
    unsigned sa = (unsigned)__cvta_generic_to_shared(dst);
    int sz = pred ? 16 : 0;
    asm volatile("cp.async.cg.shared.global [%0], [%1], 16, %2;\n"
                 :: "r"(sa), "l"(src), "r"(sz));
}
#define CP_COMMIT() asm volatile("cp.async.commit_group;\n" ::)
#define CP_WAIT1()  asm volatile("cp.async.wait_group 1;\n" ::)
#define CP_WAIT0()  asm volatile("cp.async.wait_group 0;\n" ::)

// swizzled word layouts, zero padding, all accesses conflict-free:
#define SW16(r, c)  ((r) * 16  + ((c) ^ ((((r) >> 1) & 3) * 4)))
#define SW128(r, c) ((r) * 128 + ((c) ^ (((r) & 7) * 8)))

// ---------------- 128x128x16 3-stage-pipelined tf32 GEMM tile ----------------
// Raw fp32 bits fed to mma.sync.tf32 (HW truncates).
// TA: A stored (K, M) row-major, lda; else (M, K).
// TB: B stored (N, K) row-major, ldb; else (K, N).
// MASK: apply attention masks in epilogue.
template <bool TA, bool TB, bool MASK>
__device__ __forceinline__ void gemm_mma(const float* __restrict__ A,
                                         const float* __restrict__ Bm,
                                         float* __restrict__ C,
                                         int M, int N, int K,
                                         int lda, int ldb, int ldc,
                                         float alpha, int row0, int col0,
                                         const int* __restrict__ rowmask,
                                         const int* __restrict__ colmask)
{
    __shared__ unsigned sAb[STAGES][TILE_W];
    __shared__ unsigned sBb[STAGES][TILE_W];

    const int tid  = threadIdx.x;
    const int lane = tid & 31;
    const int wid  = tid >> 5;
    const int wm   = (wid >> 1) * 32;
    const int wn   = (wid & 1) * 64;

    float acc[2][8][4];
#pragma unroll
    for (int i = 0; i < 2; i++)
#pragma unroll
        for (int j = 0; j < 8; j++)
#pragma unroll
            for (int t = 0; t < 4; t++) acc[i][j][t] = 0.0f;

    const int nTiles = K / BK;

    auto issue = [&](int buf, int k0) {
        unsigned* sA = sAb[buf];
        unsigned* sB = sBb[buf];
#pragma unroll
        for (int it = 0; it < 2; it++) {
            int idx = tid + it * 256;
            if (!TA) {
                int m  = idx >> 2;
                int kk = (idx & 3) * 4;
                cpasync16(&sA[SW16(m, kk)],
                          &A[(long)(row0 + m) * lda + k0 + kk], true);
            } else {
                int kk = idx >> 5;
                int m4 = (idx & 31) * 4;
                cpasync16(&sA[SW128(kk, m4)],
                          &A[(long)(k0 + kk) * lda + row0 + m4], true);
            }
        }
#pragma unroll
        for (int it = 0; it < 2; it++) {
            int idx = tid + it * 256;
            if (!TB) {
                int kk = idx >> 5;
                int n4 = (idx & 31) * 4;
                cpasync16(&sB[SW128(kk, n4)],
                          &Bm[(long)(k0 + kk) * ldb + col0 + n4],
                          col0 + n4 < N);
            } else {
                int n  = idx >> 2;
                int kq = (idx & 3) * 4;
                cpasync16(&sB[SW16(n, kq)],
                          &Bm[(long)(col0 + n) * ldb + k0 + kq],
                          col0 + n < N);
            }
        }
        CP_COMMIT();
    };

    const int arq = lane >> 2;
    const int ac  = lane & 3;

    issue(0, 0);
    if (nTiles > 1) issue(1, BK);

    for (int t = 0; t < nTiles; t++) {
        const int buf = t % STAGES;
        unsigned* sA = sAb[buf];
        unsigned* sB = sBb[buf];

        if (t + 1 < nTiles) CP_WAIT1(); else CP_WAIT0();
        __syncthreads();
        if (t + 2 < nTiles) issue((t + 2) % STAGES, (t + 2) * BK);

#pragma unroll
        for (int kc = 0; kc < BK; kc += 8) {
            unsigned af0[4], af1[4];
            if (!TA) {
                af0[0] = sA[SW16(wm + arq,      kc + ac)];
                af0[1] = sA[SW16(wm + arq + 8,  kc + ac)];
                af0[2] = sA[SW16(wm + arq,      kc + ac + 4)];
                af0[3] = sA[SW16(wm + arq + 8,  kc + ac + 4)];
                af1[0] = sA[SW16(wm + arq + 16, kc + ac)];
                af1[1] = sA[SW16(wm + arq + 24, kc + ac)];
                af1[2] = sA[SW16(wm + arq + 16, kc + ac + 4)];
                af1[3] = sA[SW16(wm + arq + 24, kc + ac + 4)];
            } else {
                af0[0] = sA[SW128(kc + ac,     wm + arq)];
                af0[1] = sA[SW128(kc + ac,     wm + arq + 8)];
                af0[2] = sA[SW128(kc + ac + 4, wm + arq)];
                af0[3] = sA[SW128(kc + ac + 4, wm + arq + 8)];
                af1[0] = sA[SW128(kc + ac,     wm + arq + 16)];
                af1[1] = sA[SW128(kc + ac,     wm + arq + 24)];
                af1[2] = sA[SW128(kc + ac + 4, wm + arq + 16)];
                af1[3] = sA[SW128(kc + ac + 4, wm + arq + 24)];
            }
#pragma unroll
            for (int j = 0; j < 8; j++) {
                const int bn = wn + j * 8 + arq;
                unsigned b0, b1;
                if (!TB) {
                    b0 = sB[SW128(kc + ac,     bn)];
                    b1 = sB[SW128(kc + ac + 4, bn)];
                } else {
                    b0 = sB[SW16(bn, kc + ac)];
                    b1 = sB[SW16(bn, kc + ac + 4)];
                }
                mma_tf32(acc[0][j], af0, b0, b1);
                mma_tf32(acc[1][j], af1, b0, b1);
            }
        }
    }

    // ---- epilogue ----
#pragma unroll
    for (int i = 0; i < 2; i++) {
        int r  = row0 + wm + i * 16 + arq;
        int rv0 = 1, rv1 = 1;
        if (MASK) { rv0 = rowmask[r]; rv1 = rowmask[r + 8]; }
#pragma unroll
        for (int j = 0; j < 8; j++) {
            int c = col0 + wn + j * 8 + ac * 2;
            if (c < N) {
                float v0 = alpha * acc[i][j][0];
                float v1 = alpha * acc[i][j][1];
                float v2 = alpha * acc[i][j][2];
                float v3 = alpha * acc[i][j][3];
                if (MASK) {
                    int cm0 = colmask[c], cm1 = colmask[c + 1];
                    if (rv0 == 0 || cm0 == 0) v0 = NEG_F;
                    if (rv0 == 0 || cm1 == 0) v1 = NEG_F;
                    if (rv1 == 0 || cm0 == 0) v2 = NEG_F;
                    if (rv1 == 0 || cm1 == 0) v3 = NEG_F;
                }
                *(float2*)&C[(long)r * ldc + c]       = make_float2(v0, v1);
                *(float2*)&C[(long)(r + 8) * ldc + c] = make_float2(v2, v3);
            }
        }
    }
}

// ---------------- fused projection mega-kernel ----------------
// grid (6, 544): by<16 -> q, by<32 -> vq, by<288 -> k, else vp
__global__ void __launch_bounds__(256, 2)
k_proj_all(const float* __restrict__ pep, const float* __restrict__ prot,
           const float* __restrict__ Wq,  const float* __restrict__ Wvq,
           const float* __restrict__ Wk,  const float* __restrict__ Wvp,
           float* __restrict__ q, float* __restrict__ vq,
           float* __restrict__ k, float* __restrict__ vp)
{
    int by = blockIdx.y;
    const float *A, *Bm; float* C; int row0;
    if (by < 16)        { A = pep;  Bm = Wq;  C = q;  row0 = by * BM; }
    else if (by < 32)   { A = pep;  Bm = Wvq; C = vq; row0 = (by - 32 + 16) * BM; }
    else if (by < 288)  { A = prot; Bm = Wk;  C = k;  row0 = (by - 32) * BM; }
    else                { A = prot; Bm = Wvp; C = vp; row0 = (by - 288) * BM; }
    gemm_mma<false, false, false>(A, Bm, C, 0, INNER, INNER,
                                  INNER, INNER, INNER, 1.0f,
                                  row0, blockIdx.x * BN, 0, 0);
}

// scores with fused masking: writes NEG_F where masked
__global__ void __launch_bounds__(256, 2)
k_scores(const float* __restrict__ q, const float* __restrict__ kb,
         float* __restrict__ attn,
         const int* __restrict__ pmask, const int* __restrict__ promask)
{
    int z = blockIdx.z;
    int b = z >> 3, h = z & 7;
    const float* A  = q  + (long)b * N_PEP * INNER + h * DH;
    const float* Bm = kb + (long)b * M_PRO * INNER + h * DH;
    float* C = attn + (long)z * N_PEP * M_PRO;
    gemm_mma<false, true, true>(A, Bm, C, N_PEP, M_PRO, DH,
                                INNER, INNER, M_PRO, SCALE_F,
                                blockIdx.y * BM, blockIdx.x * BN,
                                pmask + b * N_PEP, promask + b * M_PRO);
}

// fused context mega-kernel: z<512 -> ctxprot split-K chunk; z>=512 -> ctxpep tile
__global__ void __launch_bounds__(256, 2)
k_ctx_all(const float* __restrict__ attn, const float* __restrict__ vp,
          const float* __restrict__ vq, float* __restrict__ part,
          float* __restrict__ cq)
{
    int z = blockIdx.z;
    if (z < BATCH * HEADS * KSPLIT) {
        int bh = z >> 2, chunk = z & 3;
        int b = bh >> 3, h = bh & 7;
        const float* A  = attn + (long)bh * N_PEP * M_PRO + chunk * KCHUNK;
        const float* Bm = vp + (long)b * M_PRO * INNER + (long)chunk * KCHUNK * INNER + h * DH;
        float* C = part + (long)chunk * (BATCH * N_PEP * INNER)
                        + (long)b * N_PEP * INNER + h * DH;
        gemm_mma<false, false, false>(A, Bm, C, N_PEP, DH, KCHUNK,
                                      M_PRO, INNER, INNER, 1.0f, 0, 0, 0, 0);
    } else {
        int idx = z - BATCH * HEADS * KSPLIT;    // 0..2047
        int bh = idx >> 4, ry = idx & 15;
        int b = bh >> 3, h = bh & 7;
        const float* A  = attn + (long)bh * N_PEP * M_PRO;   // (K=n, M=m)
        const float* Bm = vq + (long)b * N_PEP * INNER + h * DH;
        float* C = cq + (long)b * M_PRO * INNER + h * DH;
        gemm_mma<true, false, false>(A, Bm, C, M_PRO, DH, N_PEP,
                                     M_PRO, INNER, INNER, 1.0f,
                                     ry * BM, 0, 0, 0);
    }
}

// reduce 4 partials -> cp
__global__ void __launch_bounds__(256)
k_reduce4(const float* __restrict__ part, float* __restrict__ cp)
{
    const long STRIDE = (long)BATCH * N_PEP * INNER;
    long i = ((long)blockIdx.x * 256 + threadIdx.x) * 4;
    if (i >= STRIDE) return;
    float4 a = *(const float4*)&part[i];
    float4 b = *(const float4*)&part[STRIDE + i];
    float4 c = *(const float4*)&part[2 * STRIDE + i];
    float4 d = *(const float4*)&part[3 * STRIDE + i];
    *(float4*)&cp[i] = make_float4(a.x + b.x + c.x + d.x, a.y + b.y + c.y + d.y,
                                   a.z + b.z + c.z + d.z, a.w + b.w + c.w + d.w);
}

// fused output projections: by<256 -> y2 (cq@Woq), else -> y1 (cp@Wop)
__global__ void __launch_bounds__(256, 2)
k_out_dual(const float* __restrict__ cq, const float* __restrict__ Woq,
           float* __restrict__ y2,
           const float* __restrict__ cp, const float* __restrict__ Wop,
           float* __restrict__ y1)
{
    if (blockIdx.y < 256) {
        gemm_mma<false, false, false>(cq, Woq, y2, BATCH * M_PRO, INNER, INNER,
                                      INNER, INNER, INNER, 1.0f,
                                      blockIdx.y * BM, blockIdx.x * BN, 0, 0);
    } else {
        gemm_mma<false, false, false>(cp, Wop, y1, BATCH * N_PEP, INNER, INNER,
                                      INNER, INNER, INNER, 1.0f,
                                      (blockIdx.y - 256) * BM, blockIdx.x * BN, 0, 0);
    }
}

// ---------------- softmax (masks pre-applied as NEG_F) ----------------
__global__ void __launch_bounds__(256)
k_softmax(float* __restrict__ attn)
{
    const int tid = threadIdx.x;
    float* p = attn + (long)blockIdx.x * M_PRO;

    float4 v0 = *(float4*)&p[tid * 4];
    float4 v1 = *(float4*)&p[1024 + tid * 4];

    float mx = fmaxf(fmaxf(fmaxf(v0.x, v0.y), fmaxf(v0.z, v0.w)),
                     fmaxf(fmaxf(v1.x, v1.y), fmaxf(v1.z, v1.w)));
#pragma unroll
    for (int o = 16; o; o >>= 1)
        mx = fmaxf(mx, __shfl_xor_sync(0xffffffff, mx, o));
    __shared__ float red[8];
    if ((tid & 31) == 0) red[tid >> 5] = mx;
    __syncthreads();
    if (tid < 8) {
        float m = red[tid];
#pragma unroll
        for (int o = 4; o; o >>= 1) m = fmaxf(m, __shfl_xor_sync(0xff, m, o));
        red[tid] = m;
    }
    __syncthreads();
    mx = red[0];

    v0.x = expf(v0.x - mx); v0.y = expf(v0.y - mx);
    v0.z = expf(v0.z - mx); v0.w = expf(v0.w - mx);
    v1.x = expf(v1.x - mx); v1.y = expf(v1.y - mx);
    v1.z = expf(v1.z - mx); v1.w = expf(v1.w - mx);
    float s = v0.x + v0.y + v0.z + v0.w + v1.x + v1.y + v1.z + v1.w;
#pragma unroll
    for (int o = 16; o; o >>= 1) s += __shfl_xor_sync(0xffffffff, s, o);
    __shared__ float red2[8];
    if ((tid & 31) == 0) red2[tid >> 5] = s;
    __syncthreads();
    if (tid < 8) {
        float t = red2[tid];
#pragma unroll
        for (int o = 4; o; o >>= 1) t += __shfl_xor_sync(0xff, t, o);
        red2[tid] = t;
    }
    __syncthreads();
    float inv = 1.0f / red2[0];

    v0.x *= inv; v0.y *= inv; v0.z *= inv; v0.w *= inv;
    v1.x *= inv; v1.y *= inv; v1.z *= inv; v1.w *= inv;
    *(float4*)&p[tid * 4] = v0;
    *(float4*)&p[1024 + tid * 4] = v1;
}

// ---------------- fused LN ----------------
__global__ void __launch_bounds__(256)
k_ln_dual(const float* __restrict__ y1, const float* __restrict__ bo1,
          const float* __restrict__ res1, float* __restrict__ out1,
          const float* __restrict__ y2, const float* __restrict__ bo2,
          const float* __restrict__ res2, float* __restrict__ out2,
          const float* __restrict__ g, const float* __restrict__ beta)
{
    const int NROW1 = BATCH * N_PEP;   // 2048
    int row = blockIdx.x;
    const float *y, *bo, *r; float* out; int lrow;
    if (row < NROW1) { y = y1; bo = bo1; r = res1; out = out1; lrow = row; }
    else             { y = y2; bo = bo2; r = res2; out = out2; lrow = row - NROW1; }
    int tid = threadIdx.x;
    const float* yp = y + (long)lrow * INNER;
    const float* rp = r + (long)lrow * INNER;

    float x[3];
    float s = 0.0f;
#pragma unroll
    for (int i = 0; i < 3; i++) {
        int c = tid + i * 256;
        x[i] = yp[c] + bo[c] + rp[c];
        s += x[i];
    }
#pragma unroll
    for (int o = 16; o; o >>= 1) s += __shfl_xor_sync(0xffffffff, s, o);
    __shared__ float red[8];
    if ((tid & 31) == 0) red[tid >> 5] = s;
    __syncthreads();
    if (tid < 8) {
        float t = red[tid];
#pragma unroll
        for (int o = 4; o; o >>= 1) t += __shfl_xor_sync(0xff, t, o);
        red[tid] = t;
    }
    __syncthreads();
    float mu = red[0] * (1.0f / INNER);

    float v = 0.0f;
#pragma unroll
    for (int i = 0; i < 3; i++) { float d = x[i] - mu; v += d * d; }
#pragma unroll
    for (int o = 16; o; o >>= 1) v += __shfl_xor_sync(0xffffffff, v, o);
    __shared__ float red2[8];
    if ((tid & 31) == 0) red2[tid >> 5] = v;
    __syncthreads();
    if (tid < 8) {
        float t = red2[tid];
#pragma unroll
        for (int o = 4; o; o >>= 1) t += __shfl_xor_sync(0xff, t, o);
        red2[tid] = t;
    }
    __syncthreads();
    float rstd = rsqrtf(red2[0] * (1.0f / INNER) + EPS_F);
#pragma unroll
    for (int i = 0; i < 3; i++) {
        int c = tid + i * 256;
        out[(long)lrow * INNER + c] = (x[i] - mu) * rstd * g[c] + beta[c];
    }
}

// ---------------- launch ----------------
extern "C" void kernel_launch(void* const* d_in, const int* in_sizes, int n_in,
                              void* d_out, int out_size)
{
    const float* peptide = (const float*)d_in[0];
    const float* protein = (const float*)d_in[1];
    const int*   pmask   = (const int*)  d_in[2];
    const int*   promask = (const int*)  d_in[3];
    const float* Wq      = (const float*)d_in[4];
    const float* Wk      = (const float*)d_in[5];
    const float* Wvp     = (const float*)d_in[6];
    const float* Wvq     = (const float*)d_in[7];
    const float* Wop     = (const float*)d_in[8];
    const float* bop     = (const float*)d_in[9];
    const float* Woq     = (const float*)d_in[10];
    const float* boq     = (const float*)d_in[11];
    const float* lng     = (const float*)d_in[12];
    const float* lnb     = (const float*)d_in[13];

    float* out = (float*)d_out;
    float* out_prot = out;                                   // (16,128,768)
    float* out_pep  = out + (long)BATCH * N_PEP * INNER;     // (16,2048,768)
    float* attn     = out_pep + (long)BATCH * M_PRO * INNER; // (16,8,128,2048)

    float *q, *k, *vp, *vq, *cp, *cq, *y1, *y2, *part;
    cudaGetSymbolAddress((void**)&q,  g_q);
    cudaGetSymbolAddress((void**)&k,  g_k);
    cudaGetSymbolAddress((void**)&vp, g_vp);
    cudaGetSymbolAddress((void**)&vq, g_vq);
    cudaGetSymbolAddress((void**)&cp, g_cp);
    cudaGetSymbolAddress((void**)&cq, g_cq);
    cudaGetSymbolAddress((void**)&y1, g_y1);
    cudaGetSymbolAddress((void**)&y2, g_y2);
    cudaGetSymbolAddress((void**)&part, g_part);

    const dim3 blk(256);

    // all four projections in one launch
    k_proj_all<<<dim3(6, 544), blk>>>(peptide, protein, Wq, Wvq, Wk, Wvp,
                                      q, vq, k, vp);

    // attention scores (mask fused) + softmax (attn lives in d_out)
    k_scores <<<dim3(16, 1, BATCH * HEADS), blk>>>(q, k, attn, pmask, promask);
    k_softmax<<<BATCH * HEADS * N_PEP, 256>>>(attn);

    // both context GEMMs in one launch
    k_ctx_all<<<dim3(1, 1, BATCH * HEADS * KSPLIT + BATCH * HEADS * 16), blk>>>(
        attn, vp, vq, part, cq);
    k_reduce4<<<(BATCH * N_PEP * INNER / 4 + 255) / 256, blk>>>(part, cp);

    // output projections (y2 + y1 fused into one launch)
    k_out_dual<<<dim3(6, 272), blk>>>(cq, Woq, y2, cp, Wop, y1);

    // bias + residual + layernorm (fused)
    k_ln_dual<<<BATCH * N_PEP + BATCH * M_PRO, 256>>>(
        y1, bop, peptide, out_prot, y2, boq, protein, out_pep, lng, lnb);
}